// round 6
// baseline (speedup 1.0000x reference)
#include <cuda_runtime.h>
#include <cuda_fp16.h>

// Problem constants
#define B_DIM 2048
#define IN_DIM 8192
#define O_DIM 4096
#define K_DIM 64

// 32 MB transposed fp16 copy of x: xth[i][b] (b contiguous, L2-resident)
__device__ __half g_xth[(size_t)IN_DIM * B_DIM];

// ---------------------------------------------------------------------------
// Kernel 1: transpose+convert x[B, IN] f32 -> g_xth[IN, B] f16.
// ---------------------------------------------------------------------------
__global__ __launch_bounds__(256) void transpose_kernel(const float* __restrict__ x) {
    __shared__ float tile[32][33];
    const int i0 = blockIdx.x * 32;
    const int b0 = blockIdx.y * 32;
    const int tx = threadIdx.x;
    const int ty = threadIdx.y;

#pragma unroll
    for (int j = 0; j < 4; j++) {
        tile[ty + j * 8][tx] = x[(size_t)(b0 + ty + j * 8) * IN_DIM + (i0 + tx)];
    }
    __syncthreads();
#pragma unroll
    for (int j = 0; j < 4; j++) {
        g_xth[(size_t)(i0 + ty + j * 8) * B_DIM + (b0 + tx)] = __float2half(tile[tx][ty + j * 8]);
    }
}

// ---------------------------------------------------------------------------
// Kernel 2: gather + weighted reduce (fp16 xt, fp32 accumulate).
// R4 ncu: occ=36% (3 ragged CTAs/SM), issue=45%, L2=45% -> issue/latency bound.
// R5: 128-thread CTAs, B split in 2 -> grid (2,512)=1024 CTAs, 8 CTAs/SM
//     (launch_bounds(128,8)) => 32 warps/SM. idx+w fused into one int2 smem
//     array -> single LDS.64 per inner iter.
// Thread owns 8 consecutive b (one uint4 of halves); block covers 1024 b.
// ---------------------------------------------------------------------------
#define OT 8
#define OACC 2
#define NTHR 128

__global__ __launch_bounds__(NTHR, 8) void gather_kernel(const int* __restrict__ indices,
                                                         const float* __restrict__ weight,
                                                         const float* __restrict__ bias,
                                                         float* __restrict__ out) {
    __shared__ int2 s_iw[OT * K_DIM];  // 4 KB: {premultiplied row offset, w bits}

    const int tid = threadIdx.x;
    const int obase = blockIdx.y * OT;
    const int bq = blockIdx.x * NTHR + tid;  // uint4 index within an xt row (row = B/8 uint4)
    const int brow = bq * 8;                 // first of this thread's 8 b's

    // Stage indices (premultiplied by uint4-row stride) + weights, fused
    for (int t = tid; t < OT * K_DIM; t += NTHR) {
        int2 iw;
        iw.x = indices[(size_t)obase * K_DIM + t] * (B_DIM / 8);
        iw.y = __float_as_int(weight[(size_t)obase * K_DIM + t]);
        s_iw[t] = iw;
    }
    __syncthreads();

    const uint4* __restrict__ xt8 = (const uint4*)g_xth;

    for (int og = 0; og < OT; og += OACC) {
        float acc[OACC][8];
#pragma unroll
        for (int j = 0; j < OACC; j++)
#pragma unroll
            for (int q = 0; q < 8; q++) acc[j][q] = 0.f;

#pragma unroll 4
        for (int k = 0; k < K_DIM; k++) {
#pragma unroll
            for (int j = 0; j < OACC; j++) {
                const int2 iw = s_iw[(og + j) * K_DIM + k];  // one LDS.64
                const float w = __int_as_float(iw.y);
                const uint4 v = xt8[iw.x + bq];              // 8 halves, coalesced along b
                const __half2* h = (const __half2*)&v;
#pragma unroll
                for (int q = 0; q < 4; q++) {
                    const float2 f = __half22float2(h[q]);
                    acc[j][2 * q + 0] += f.x * w;
                    acc[j][2 * q + 1] += f.y * w;
                }
            }
        }

        float bv[OACC];
#pragma unroll
        for (int j = 0; j < OACC; j++) bv[j] = bias[obase + og + j];

#pragma unroll
        for (int bb = 0; bb < 8; bb++) {
            float2 v;
            v.x = acc[0][bb] + bv[0];
            v.y = acc[1][bb] + bv[1];
            *(float2*)(out + (size_t)(brow + bb) * O_DIM + obase + og) = v;
        }
    }
}

// ---------------------------------------------------------------------------
// Launch
// ---------------------------------------------------------------------------
extern "C" void kernel_launch(void* const* d_in, const int* in_sizes, int n_in,
                              void* d_out, int out_size) {
    (void)in_sizes; (void)n_in; (void)out_size;
    const float* x = (const float*)d_in[0];
    const int* indices = (const int*)d_in[1];
    const float* weight = (const float*)d_in[2];
    const float* bias = (const float*)d_in[3];
    float* out = (float*)d_out;

    dim3 tb(32, 8);
    dim3 tg(IN_DIM / 32, B_DIM / 32);  // (256, 64)
    transpose_kernel<<<tg, tb>>>(x);

    dim3 gg(B_DIM / (NTHR * 8), O_DIM / OT);  // (2, 512) = 1024 CTAs
    gather_kernel<<<gg, NTHR>>>(indices, weight, bias, out);
}